// round 9
// baseline (speedup 1.0000x reference)
#include <cuda_runtime.h>
#include <stdint.h>
#include <math.h>

#define TT 2048
#define BB 16
#define NN 2048
#define HH 1024
#define SPL 32
#define CHUNK 64    // timesteps per CTA; 16 macro-iters of 4
#define THR 256     // k_main threads (8 warps), 2 CTAs/SM

// scratch (device globals: no allocation allowed in kernel_launch)
__device__ float g_decfea[BB*NN];
__device__ float g_scores[TT*BB];
__device__ float g_m[BB*SPL];
__device__ float g_z[BB*SPL];
__device__ float g_acc[BB*SPL*NN];     // 4 MB
__device__ unsigned char g_mask8[TT*BB];

__device__ __forceinline__ float ex2f(float x){
    float y; asm("ex2.approx.f32 %0, %1;" : "=f"(y) : "f"(x)); return y;
}
__device__ __forceinline__ float rcpf(float x){
    float y; asm("rcp.approx.f32 %0, %1;" : "=f"(y) : "f"(x)); return y;
}

__device__ __forceinline__ float4 ldcs4(const float4* p){
    float4 r;
    asm("ld.global.cs.v4.f32 {%0,%1,%2,%3}, [%4];"
        : "=f"(r.x), "=f"(r.y), "=f"(r.z), "=f"(r.w) : "l"(p));
    return r;
}

// ---------------------------------------------------------------------------
// Kernel 1: dec_fea[b,n] = dot(dec[b,:], Wd[n,:]) + bd[n].
// 256 CTAs x 256 thr; warp owns one n-row. All 8 Wd float4s preloaded up
// front (8 LDG.128 in flight per warp -> MLP-limited latency halves).
// All 16 dec batches staged once in 64 KB dynamic smem. Full-butterfly
// reduce; lane b stores batch b. Also converts padding mask to uint8.
// ---------------------------------------------------------------------------
__global__ __launch_bounds__(256) void k_decfea(
    const float* __restrict__ dec,
    const float* __restrict__ Wd,
    const float* __restrict__ bd,
    const unsigned char* __restrict__ mraw){
    extern __shared__ float sdec[];    // 64 KB: all 16 batches of dec
    // ---- mask conversion (65536 lanes cover 32768 elems) ----
    {
        const unsigned int* w = (const unsigned int*)mraw;
        int is_word = 1;   // int32 (0/1) or float32 (0.0/1.0) storage
        #pragma unroll
        for (int i = 0; i < 32; ++i){
            unsigned int x = w[i];
            if (x != 0u && x != 1u && x != 0x3F800000u) is_word = 0;
        }
        int idx = blockIdx.x*256 + threadIdx.x;
        if (idx < TT*BB){
            unsigned char mv = is_word ? (unsigned char)(w[idx] != 0u)
                                       : (unsigned char)(mraw[idx] != 0);
            g_mask8[idx] = mv;
        }
    }

    int tid  = threadIdx.x;
    int wid  = tid >> 5, lane = tid & 31;

    int n = blockIdx.x*8 + wid;        // this warp's row
    const float4* wp = (const float4*)(Wd + (size_t)n*HH);

    // preload all 8 Wd chunks (independent LDGs, high MLP)
    float4 wv[8];
    #pragma unroll
    for (int ch = 0; ch < 8; ++ch) wv[ch] = wp[ch*32 + lane];

    // stage all of dec (16*1024 floats)
    {
        const float4* dg = (const float4*)dec;
        float4* sg = (float4*)sdec;
        #pragma unroll
        for (int i = 0; i < 16; ++i) sg[tid + i*256] = dg[tid + i*256];
    }
    __syncthreads();

    const float4* sd = (const float4*)sdec;
    float acc[BB];
    #pragma unroll
    for (int b = 0; b < BB; ++b) acc[b] = 0.f;

    #pragma unroll
    for (int ch = 0; ch < 8; ++ch){
        #pragma unroll
        for (int b = 0; b < BB; ++b){
            float4 d = sd[b*256 + ch*32 + lane];
            acc[b] += wv[ch].x*d.x + wv[ch].y*d.y + wv[ch].z*d.z + wv[ch].w*d.w;
        }
    }
    // full butterfly: every lane ends with all sums
    #pragma unroll
    for (int b = 0; b < BB; ++b){
        #pragma unroll
        for (int off = 16; off; off >>= 1)
            acc[b] += __shfl_xor_sync(0xffffffffu, acc[b], off);
    }
    float bias = bd[n];
    if (lane < BB) g_decfea[lane*NN + n] = acc[lane] + bias;
}

// ---------------------------------------------------------------------------
// Kernel 2: fused scores + online softmax + context partial (flash-style).
// grid (SPL, BB) = 512 CTAs; 256 threads; 2 CTAs/SM. Each thread owns 8
// contiguous n; 4 timesteps per macro-iter; 1-iter register prefetch.
// tanh via EX2+RCP (rt_SMSP=8 each) instead of the slow MUFU TANH:
//   tanh(x) = 1 - 2/(1 + 2^(K*x)),  K = 2*log2(e)
// folded:   score contrib = vsum + sum v2_j * rcp(1 + ex2(K*c + dfK + cv*wK))
// with wK = K*w, dfK = K*df, v2 = -2*v, vsum = sum(v) per thread.
// ---------------------------------------------------------------------------
__global__ __launch_bounds__(THR, 2) void k_main(
    const float* __restrict__ enc,
    const float* __restrict__ cov,
    const float* __restrict__ wc,
    const float* __restrict__ v)
{
    __shared__ float scov[CHUNK];
    __shared__ unsigned char smask[CHUNK];
    __shared__ float sred[8][5];      // [warp][score], padded
    __shared__ float sbc[4];
    int tid  = threadIdx.x;
    int wid  = tid >> 5, lane = tid & 31;
    int sp = blockIdx.x, b = blockIdx.y;
    int t0 = sp * CHUNK;

    if (tid < CHUNK){
        scov[tid]  = cov[(t0 + tid)*BB + b];
        smask[tid] = g_mask8[(t0 + tid)*BB + b];
    }
    const float K = 2.885390081777927f;   // 2*log2(e)
    int n0 = tid * 8;
    float4 df0 = *(const float4*)(g_decfea + b*NN + n0);
    float4 df1 = *(const float4*)(g_decfea + b*NN + n0 + 4);
    float4 w0  = *(const float4*)(wc + n0);
    float4 w1  = *(const float4*)(wc + n0 + 4);
    float4 v0  = *(const float4*)(v + n0);
    float4 v1  = *(const float4*)(v + n0 + 4);
    // folded constants
    df0.x*=K; df0.y*=K; df0.z*=K; df0.w*=K;
    df1.x*=K; df1.y*=K; df1.z*=K; df1.w*=K;
    w0.x*=K;  w0.y*=K;  w0.z*=K;  w0.w*=K;
    w1.x*=K;  w1.y*=K;  w1.z*=K;  w1.w*=K;
    float vsum = v0.x+v0.y+v0.z+v0.w + v1.x+v1.y+v1.z+v1.w;
    v0.x*=-2.f; v0.y*=-2.f; v0.z*=-2.f; v0.w*=-2.f;   // v2 lanes
    v1.x*=-2.f; v1.y*=-2.f; v1.z*=-2.f; v1.w*=-2.f;

    float m = -INFINITY, Z = 0.f;
    float4 A0 = make_float4(0.f,0.f,0.f,0.f);
    float4 A1 = make_float4(0.f,0.f,0.f,0.f);
    __syncthreads();

    // prefetch batch 0 (4 rows)
    float4 c0[4], c1[4];
    #pragma unroll
    for (int i = 0; i < 4; ++i){
        const float4* rp = (const float4*)(enc + ((size_t)(t0+i)*BB + b)*NN + n0);
        c0[i] = ldcs4(rp); c1[i] = ldcs4(rp + 1);
    }
    const int NB = CHUNK/4;   // 16
    for (int it = 0; it < NB; ++it){
        int tb = t0 + it*4;
        bool havenext = (it + 1 < NB);
        float4 x0[4], x1[4];
        if (havenext){
            #pragma unroll
            for (int i = 0; i < 4; ++i){
                const float4* rp = (const float4*)(enc + ((size_t)(tb+4+i)*BB + b)*NN + n0);
                x0[i] = ldcs4(rp); x1[i] = ldcs4(rp + 1);
            }
        }
        float part[4];
        #pragma unroll
        for (int i = 0; i < 4; ++i){
            float cv = scov[it*4 + i];
            float p = vsum;
            float y, u;
            y = fmaf(c0[i].x, K, df0.x); y = fmaf(cv, w0.x, y);
            u = rcpf(1.0f + ex2f(y));    p = fmaf(v0.x, u, p);
            y = fmaf(c0[i].y, K, df0.y); y = fmaf(cv, w0.y, y);
            u = rcpf(1.0f + ex2f(y));    p = fmaf(v0.y, u, p);
            y = fmaf(c0[i].z, K, df0.z); y = fmaf(cv, w0.z, y);
            u = rcpf(1.0f + ex2f(y));    p = fmaf(v0.z, u, p);
            y = fmaf(c0[i].w, K, df0.w); y = fmaf(cv, w0.w, y);
            u = rcpf(1.0f + ex2f(y));    p = fmaf(v0.w, u, p);
            y = fmaf(c1[i].x, K, df1.x); y = fmaf(cv, w1.x, y);
            u = rcpf(1.0f + ex2f(y));    p = fmaf(v1.x, u, p);
            y = fmaf(c1[i].y, K, df1.y); y = fmaf(cv, w1.y, y);
            u = rcpf(1.0f + ex2f(y));    p = fmaf(v1.y, u, p);
            y = fmaf(c1[i].z, K, df1.z); y = fmaf(cv, w1.z, y);
            u = rcpf(1.0f + ex2f(y));    p = fmaf(v1.z, u, p);
            y = fmaf(c1[i].w, K, df1.w); y = fmaf(cv, w1.w, y);
            u = rcpf(1.0f + ex2f(y));    p = fmaf(v1.w, u, p);
            part[i] = p;
        }
        // stage 1: warp reduce 4 partials
        #pragma unroll
        for (int i = 0; i < 4; ++i)
            #pragma unroll
            for (int off = 16; off; off >>= 1)
                part[i] += __shfl_xor_sync(0xffffffffu, part[i], off);
        if (lane == 0){
            #pragma unroll
            for (int i = 0; i < 4; ++i) sred[wid][i] = part[i];
        }
        __syncthreads();
        // stage 2: 32 threads, 8-lane groups, one score each
        if (tid < 32){
            int s  = tid >> 3;             // score 0..3
            int ww = tid & 7;              // warp 0..7
            float val = sred[ww][s];
            val += __shfl_xor_sync(0xffffffffu, val, 1);
            val += __shfl_xor_sync(0xffffffffu, val, 2);
            val += __shfl_xor_sync(0xffffffffu, val, 4);
            if (ww == 0) sbc[s] = val;
        }
        __syncthreads();
        float s[4];
        #pragma unroll
        for (int i = 0; i < 4; ++i)
            s[i] = smask[it*4 + i] ? -INFINITY : sbc[i];
        if (tid < 4) g_scores[(tb + tid)*BB + b] = s[tid];

        // online softmax update (uniform branch across the block)
        float m2 = m;
        #pragma unroll
        for (int i = 0; i < 4; ++i) m2 = fmaxf(m2, s[i]);
        if (m2 != -INFINITY){
            float sc = __expf(m - m2);             // m==-inf -> 0 (A still 0)
            float p[4];
            #pragma unroll
            for (int i = 0; i < 4; ++i) p[i] = __expf(s[i] - m2);
            Z = Z*sc + (p[0]+p[1]) + (p[2]+p[3]);
            float ax = A0.x*sc, ay = A0.y*sc, az = A0.z*sc, aw = A0.w*sc;
            float bx = A1.x*sc, by = A1.y*sc, bz = A1.z*sc, bw = A1.w*sc;
            #pragma unroll
            for (int i = 0; i < 4; ++i){
                ax = fmaf(p[i], c0[i].x, ax); ay = fmaf(p[i], c0[i].y, ay);
                az = fmaf(p[i], c0[i].z, az); aw = fmaf(p[i], c0[i].w, aw);
                bx = fmaf(p[i], c1[i].x, bx); by = fmaf(p[i], c1[i].y, by);
                bz = fmaf(p[i], c1[i].z, bz); bw = fmaf(p[i], c1[i].w, bw);
            }
            A0 = make_float4(ax, ay, az, aw);
            A1 = make_float4(bx, by, bz, bw);
            m = m2;
        }
        if (havenext){
            #pragma unroll
            for (int i = 0; i < 4; ++i){ c0[i] = x0[i]; c1[i] = x1[i]; }
        }
    }
    if (tid == 0){
        g_m[b*SPL + sp] = m;
        g_z[b*SPL + sp] = Z;
    }
    float4* op = (float4*)(g_acc + (size_t)(b*SPL + sp)*NN + n0);
    op[0] = A0; op[1] = A1;
}

// ---------------------------------------------------------------------------
// Kernel 3: combine. blocks 0..31: context c[b, n-half] (32 split partials).
// blocks 32..159: attn + coverage, float4 flat-indexed.
// ---------------------------------------------------------------------------
__global__ void k_combine(const float* __restrict__ cov,
                          float* __restrict__ out){
    int tid = threadIdx.x;
    if (blockIdx.x < 2*BB){
        // ---- context for batch b, n-half h ----
        int b = blockIdx.x >> 1, h = blockIdx.x & 1;
        __shared__ float sw[SPL];
        if (tid < 32){
            float mv = g_m[b*SPL + tid];
            float zv = g_z[b*SPL + tid];
            float M = mv;
            #pragma unroll
            for (int off = 16; off; off >>= 1)
                M = fmaxf(M, __shfl_xor_sync(0xffffffffu, M, off));
            float Zs = zv * __expf(mv - M);
            #pragma unroll
            for (int off = 16; off; off >>= 1)
                Zs += __shfl_xor_sync(0xffffffffu, Zs, off);
            float inv = 1.0f / Zs;
            sw[tid] = __expf(mv - M) * inv;
        }
        __syncthreads();
        int n0 = h*1024 + tid*4;
        float4 r = make_float4(0.f,0.f,0.f,0.f);
        #pragma unroll
        for (int s = 0; s < SPL; ++s){
            float4 x = *(const float4*)(g_acc + (size_t)(b*SPL + s)*NN + n0);
            float wgt = sw[s];
            r.x = fmaf(wgt, x.x, r.x); r.y = fmaf(wgt, x.y, r.y);
            r.z = fmaf(wgt, x.z, r.z); r.w = fmaf(wgt, x.w, r.w);
        }
        *(float4*)(out + b*NN + n0) = r;
    } else {
        // ---- attn_dist + coverage_out, float4-flat-indexed ----
        __shared__ float sM[BB], sInv[BB];
        if (tid < BB){
            int b = tid;
            float M = -INFINITY;
            #pragma unroll
            for (int s = 0; s < SPL; ++s) M = fmaxf(M, g_m[b*SPL + s]);
            float Zs = 0.f;
            #pragma unroll
            for (int s = 0; s < SPL; ++s) Zs += g_z[b*SPL + s] * __expf(g_m[b*SPL + s] - M);
            sM[b] = M; sInv[b] = 1.0f / Zs;
        }
        __syncthreads();
        int q = (blockIdx.x - 2*BB) * 256 + tid;    // 128 blocks -> 8192 quads
        int flat = q * 4;                           // covers TT*BB floats
        if (q < (TT*BB)/4){
            float4 sc = *(const float4*)(g_scores + flat);
            float4 cv = *(const float4*)(cov + flat);
            int b0 = flat & (BB-1);                 // 4 consecutive batches
            float4 a;
            a.x = __expf(sc.x - sM[b0  ]) * sInv[b0  ];
            a.y = __expf(sc.y - sM[b0+1]) * sInv[b0+1];
            a.z = __expf(sc.z - sM[b0+2]) * sInv[b0+2];
            a.w = __expf(sc.w - sM[b0+3]) * sInv[b0+3];
            *(float4*)(out + BB*NN + flat) = a;
            float4 cg = make_float4(cv.x + a.x, cv.y + a.y, cv.z + a.z, cv.w + a.w);
            *(float4*)(out + BB*NN + TT*BB + flat) = cg;
        }
    }
}

// ---------------------------------------------------------------------------
extern "C" void kernel_launch(void* const* d_in, const int* in_sizes, int n_in,
                              void* d_out, int out_size){
    const float*         dec  = (const float*)d_in[0];          // [B,H]
    const float*         enc  = (const float*)d_in[1];          // [T,B,N]
    const unsigned char* mask = (const unsigned char*)d_in[2];  // [T,B] (dtype auto-detected)
    const float*         cov  = (const float*)d_in[3];          // [T,B]
    const float*         Wd   = (const float*)d_in[4];          // [N,H]
    const float*         bd   = (const float*)d_in[5];          // [N]
    const float*         wc   = (const float*)d_in[6];          // [N]
    const float*         v    = (const float*)d_in[7];          // [N]
    float* out = (float*)d_out;  // c[B,N] | attn[T,B] | coverage_out[T,B]

    const int SMEM_DEC = BB*HH*4;                               // 64 KB
    cudaFuncSetAttribute(k_decfea, cudaFuncAttributeMaxDynamicSharedMemorySize, SMEM_DEC);

    k_decfea<<<256, 256, SMEM_DEC>>>(dec, Wd, bd, mask);
    k_main<<<dim3(SPL, BB), THR>>>(enc, cov, wc, v);
    k_combine<<<2*BB + (TT*BB/4 + 255)/256, 256>>>(cov, out);
}

// round 10
// speedup vs baseline: 1.2293x; 1.2293x over previous
#include <cuda_runtime.h>
#include <stdint.h>
#include <math.h>

#define TT 2048
#define BB 16
#define NN 2048
#define HH 1024
#define SPL 64
#define CHUNK 32    // timesteps per CTA; 8 macro-iters of 4
#define THR 256     // k_main threads (8 warps), 3 CTAs/SM

// scratch (device globals: no allocation allowed in kernel_launch)
__device__ float g_decfea[BB*NN];
__device__ float g_scores[TT*BB];
__device__ float g_m[BB*SPL];
__device__ float g_z[BB*SPL];
__device__ float g_acc[BB*SPL*NN];     // 8 MB
__device__ unsigned char g_mask8[TT*BB];

// single-MUFU tanh (sm_75+), abs err ~2e-4 — fine vs 1e-3 threshold
__device__ __forceinline__ float tanhfast(float x){
    float y;
    asm("tanh.approx.f32 %0, %1;" : "=f"(y) : "f"(x));
    return y;
}

__device__ __forceinline__ void cpasync16(unsigned int saddr, const float* g){
    asm volatile("cp.async.cg.shared.global [%0], [%1], 16;" :: "r"(saddr), "l"(g));
}
#define CP_COMMIT() asm volatile("cp.async.commit_group;" ::: "memory")
#define CP_WAIT(n)  asm volatile("cp.async.wait_group %0;" :: "n"(n) : "memory")

// ---------------------------------------------------------------------------
// Kernel 1: dec_fea[b,n] = dot(dec[b,:], Wd[n,:]) + bd[n].
// 512 CTAs x 128 thr; warp owns one n-row; NO smem: dec (64 KB) stays hot in
// L1 (every CTA reads all of it), Wd rows preloaded with MLP 8.
// Also converts the padding mask to uint8 (dtype auto-detected).
// ---------------------------------------------------------------------------
__global__ __launch_bounds__(128) void k_decfea(
    const float* __restrict__ dec,
    const float* __restrict__ Wd,
    const float* __restrict__ bd,
    const unsigned char* __restrict__ mraw){
    // ---- mask conversion (first 32768 lanes of 65536) ----
    {
        const unsigned int* w = (const unsigned int*)mraw;
        int is_word = 1;   // int32 (0/1) or float32 (0.0/1.0) storage
        #pragma unroll
        for (int i = 0; i < 32; ++i){
            unsigned int x = w[i];
            if (x != 0u && x != 1u && x != 0x3F800000u) is_word = 0;
        }
        int idx = blockIdx.x*128 + threadIdx.x;
        if (idx < TT*BB){
            unsigned char mv = is_word ? (unsigned char)(w[idx] != 0u)
                                       : (unsigned char)(mraw[idx] != 0);
            g_mask8[idx] = mv;
        }
    }

    int tid  = threadIdx.x;
    int wid  = tid >> 5, lane = tid & 31;

    int n = blockIdx.x*4 + wid;        // this warp's row (2048 rows total)
    const float4* wp = (const float4*)(Wd + (size_t)n*HH);
    const float4* dp = (const float4*)dec;

    // preload all 8 Wd chunks (independent LDGs, high MLP)
    float4 wv[8];
    #pragma unroll
    for (int ch = 0; ch < 8; ++ch) wv[ch] = wp[ch*32 + lane];

    float acc[BB];
    #pragma unroll
    for (int b = 0; b < BB; ++b) acc[b] = 0.f;

    #pragma unroll
    for (int ch = 0; ch < 8; ++ch){
        #pragma unroll
        for (int b = 0; b < BB; ++b){
            float4 d = dp[b*256 + ch*32 + lane];   // L1-hot after first touch
            acc[b] += wv[ch].x*d.x + wv[ch].y*d.y + wv[ch].z*d.z + wv[ch].w*d.w;
        }
    }
    // full butterfly: every lane ends with all sums
    #pragma unroll
    for (int b = 0; b < BB; ++b){
        #pragma unroll
        for (int off = 16; off; off >>= 1)
            acc[b] += __shfl_xor_sync(0xffffffffu, acc[b], off);
    }
    float bias = bd[n];
    if (lane < BB) g_decfea[lane*NN + n] = acc[lane] + bias;
}

// ---------------------------------------------------------------------------
// Kernel 2: fused scores + online softmax + context partial (flash-style).
// grid (SPL, BB) = 1024 CTAs; 256 threads; 3 CTAs/SM (6 warps/SMSP, staggered
// phases overlap DRAM/MUFU/issue). enc staged via 2-stage cp.async double
// buffer (32 KB/stage); regs stay ~65 -> no spills at the 85-reg cap.
// ---------------------------------------------------------------------------
__global__ __launch_bounds__(THR, 3) void k_main(
    const float* __restrict__ enc,
    const float* __restrict__ cov,
    const float* __restrict__ wc,
    const float* __restrict__ v)
{
    extern __shared__ float smem[];
    float* sbuf = smem;                          // 2 * 4*NN floats (64 KB)
    float* scov = sbuf + 2*4*NN;                 // CHUNK floats
    unsigned char* smask = (unsigned char*)(scov + CHUNK);   // CHUNK bytes
    float* sred = (float*)(smask + CHUNK + 32);  // 8*5 floats (align pad)
    float* sbc  = sred + 40;                     // 4 floats

    int tid  = threadIdx.x;
    int wid  = tid >> 5, lane = tid & 31;
    int sp = blockIdx.x, b = blockIdx.y;
    int t0 = sp * CHUNK;

    if (tid < CHUNK){
        scov[tid]  = cov[(t0 + tid)*BB + b];
        smask[tid] = g_mask8[(t0 + tid)*BB + b];
    }
    int n0 = tid * 8;
    float4 df0 = *(const float4*)(g_decfea + b*NN + n0);
    float4 df1 = *(const float4*)(g_decfea + b*NN + n0 + 4);
    float4 w0  = *(const float4*)(wc + n0);
    float4 w1  = *(const float4*)(wc + n0 + 4);
    float4 v0  = *(const float4*)(v + n0);
    float4 v1  = *(const float4*)(v + n0 + 4);

    float m = -INFINITY, Z = 0.f;
    float4 A0 = make_float4(0.f,0.f,0.f,0.f);
    float4 A1 = make_float4(0.f,0.f,0.f,0.f);

    const size_t encbase = (size_t)b*NN;
    // thread handles 8 float4s per stage: f = tid + j*256; row=f>>9; n4=f&511
    #define ISSUE_STAGE(stg, trow0)                                          \
        {                                                                    \
            unsigned int sb = (unsigned int)__cvta_generic_to_shared(        \
                              sbuf + (stg)*(4*NN));                          \
            _Pragma("unroll")                                                \
            for (int j = 0; j < 8; ++j){                                     \
                int f  = tid + j*256;                                        \
                int ri = f >> 9, n4 = f & 511;                               \
                const float* gp = enc + ((size_t)((trow0) + ri)*BB)*NN       \
                                      + encbase + n4*4;                      \
                cpasync16(sb + (unsigned int)((ri*NN + n4*4)*4), gp);        \
            }                                                                \
            CP_COMMIT();                                                     \
        }

    ISSUE_STAGE(0, t0);    // prologue: data 0

    const int NB = CHUNK/4;   // 8
    for (int it = 0; it < NB; ++it){
        int tb = t0 + it*4;
        const float* stage = sbuf + (it & 1)*(4*NN);

        CP_WAIT(0);          // data it complete (at most 1 group outstanding)
        __syncthreads();     // visible to all; prior iter's reads finished
        if (it + 1 < NB) ISSUE_STAGE((it + 1) & 1, tb + 4);

        // ---- phase A: per-thread partial dot for 4 timesteps (LDS) ----
        float part[4];
        #pragma unroll
        for (int i = 0; i < 4; ++i){
            const float4* rp = (const float4*)(stage + i*NN + n0);
            float4 ca = rp[0], cb = rp[1];
            float cv = scov[it*4 + i];
            float p;
            p  = tanhfast(fmaf(cv, w0.x, ca.x + df0.x)) * v0.x;
            p += tanhfast(fmaf(cv, w0.y, ca.y + df0.y)) * v0.y;
            p += tanhfast(fmaf(cv, w0.z, ca.z + df0.z)) * v0.z;
            p += tanhfast(fmaf(cv, w0.w, ca.w + df0.w)) * v0.w;
            p += tanhfast(fmaf(cv, w1.x, cb.x + df1.x)) * v1.x;
            p += tanhfast(fmaf(cv, w1.y, cb.y + df1.y)) * v1.y;
            p += tanhfast(fmaf(cv, w1.z, cb.z + df1.z)) * v1.z;
            p += tanhfast(fmaf(cv, w1.w, cb.w + df1.w)) * v1.w;
            part[i] = p;
        }
        // stage 1: warp reduce 4 partials
        #pragma unroll
        for (int i = 0; i < 4; ++i)
            #pragma unroll
            for (int off = 16; off; off >>= 1)
                part[i] += __shfl_xor_sync(0xffffffffu, part[i], off);
        if (lane == 0){
            #pragma unroll
            for (int i = 0; i < 4; ++i) sred[wid*5 + i] = part[i];
        }
        __syncthreads();
        // stage 2: 32 threads, 8-lane groups, one score each
        if (tid < 32){
            int s  = tid >> 3;             // score 0..3
            int ww = tid & 7;              // warp 0..7
            float val = sred[ww*5 + s];
            val += __shfl_xor_sync(0xffffffffu, val, 1);
            val += __shfl_xor_sync(0xffffffffu, val, 2);
            val += __shfl_xor_sync(0xffffffffu, val, 4);
            if (ww == 0) sbc[s] = val;
        }
        __syncthreads();
        float s[4];
        #pragma unroll
        for (int i = 0; i < 4; ++i)
            s[i] = smask[it*4 + i] ? -INFINITY : sbc[i];
        if (tid < 4) g_scores[(tb + tid)*BB + b] = s[tid];

        // online softmax update + context accumulate (re-read stage via LDS)
        float m2 = m;
        #pragma unroll
        for (int i = 0; i < 4; ++i) m2 = fmaxf(m2, s[i]);
        if (m2 != -INFINITY){
            float sc = __expf(m - m2);             // m==-inf -> 0 (A still 0)
            float p[4];
            #pragma unroll
            for (int i = 0; i < 4; ++i) p[i] = __expf(s[i] - m2);
            Z = Z*sc + (p[0]+p[1]) + (p[2]+p[3]);
            float ax = A0.x*sc, ay = A0.y*sc, az = A0.z*sc, aw = A0.w*sc;
            float bx = A1.x*sc, by = A1.y*sc, bz = A1.z*sc, bw = A1.w*sc;
            #pragma unroll
            for (int i = 0; i < 4; ++i){
                const float4* rp = (const float4*)(stage + i*NN + n0);
                float4 ca = rp[0], cb = rp[1];
                ax = fmaf(p[i], ca.x, ax); ay = fmaf(p[i], ca.y, ay);
                az = fmaf(p[i], ca.z, az); aw = fmaf(p[i], ca.w, aw);
                bx = fmaf(p[i], cb.x, bx); by = fmaf(p[i], cb.y, by);
                bz = fmaf(p[i], cb.z, bz); bw = fmaf(p[i], cb.w, bw);
            }
            A0 = make_float4(ax, ay, az, aw);
            A1 = make_float4(bx, by, bz, bw);
            m = m2;
        }
    }
    if (tid == 0){
        g_m[b*SPL + sp] = m;
        g_z[b*SPL + sp] = Z;
    }
    float4* op = (float4*)(g_acc + (size_t)(b*SPL + sp)*NN + n0);
    op[0] = A0; op[1] = A1;
    #undef ISSUE_STAGE
}

// ---------------------------------------------------------------------------
// Kernel 3: combine. blocks 0..31: context c[b, n-half] (64 split partials).
// blocks 32..159: attn + coverage, float4 flat-indexed.
// ---------------------------------------------------------------------------
__global__ void k_combine(const float* __restrict__ cov,
                          float* __restrict__ out){
    int tid = threadIdx.x;
    if (blockIdx.x < 2*BB){
        // ---- context for batch b, n-half h ----
        int b = blockIdx.x >> 1, h = blockIdx.x & 1;
        __shared__ float sw[SPL];
        if (tid < 32){
            // 64 splits: each lane owns (lane, lane+32)
            float m0 = g_m[b*SPL + tid],      z0 = g_z[b*SPL + tid];
            float m1 = g_m[b*SPL + tid + 32], z1 = g_z[b*SPL + tid + 32];
            float M = fmaxf(m0, m1);
            #pragma unroll
            for (int off = 16; off; off >>= 1)
                M = fmaxf(M, __shfl_xor_sync(0xffffffffu, M, off));
            float Zs = z0*__expf(m0 - M) + z1*__expf(m1 - M);
            #pragma unroll
            for (int off = 16; off; off >>= 1)
                Zs += __shfl_xor_sync(0xffffffffu, Zs, off);
            float inv = 1.0f / Zs;
            sw[tid]      = __expf(m0 - M) * inv;
            sw[tid + 32] = __expf(m1 - M) * inv;
        }
        __syncthreads();
        int n0 = h*1024 + tid*4;
        float4 r = make_float4(0.f,0.f,0.f,0.f);
        #pragma unroll
        for (int s = 0; s < SPL; ++s){
            float4 x = *(const float4*)(g_acc + (size_t)(b*SPL + s)*NN + n0);
            float wgt = sw[s];
            r.x = fmaf(wgt, x.x, r.x); r.y = fmaf(wgt, x.y, r.y);
            r.z = fmaf(wgt, x.z, r.z); r.w = fmaf(wgt, x.w, r.w);
        }
        *(float4*)(out + b*NN + n0) = r;
    } else {
        // ---- attn_dist + coverage_out, float4-flat-indexed ----
        __shared__ float sM[BB], sInv[BB];
        if (tid < BB){
            int b = tid;
            float M = -INFINITY;
            #pragma unroll
            for (int s = 0; s < SPL; ++s) M = fmaxf(M, g_m[b*SPL + s]);
            float Zs = 0.f;
            #pragma unroll
            for (int s = 0; s < SPL; ++s) Zs += g_z[b*SPL + s] * __expf(g_m[b*SPL + s] - M);
            sM[b] = M; sInv[b] = 1.0f / Zs;
        }
        __syncthreads();
        int q = (blockIdx.x - 2*BB) * 256 + tid;    // 128 blocks -> 8192 quads
        int flat = q * 4;                           // covers TT*BB floats
        if (q < (TT*BB)/4){
            float4 sc = *(const float4*)(g_scores + flat);
            float4 cv = *(const float4*)(cov + flat);
            int b0 = flat & (BB-1);                 // 4 consecutive batches
            float4 a;
            a.x = __expf(sc.x - sM[b0  ]) * sInv[b0  ];
            a.y = __expf(sc.y - sM[b0+1]) * sInv[b0+1];
            a.z = __expf(sc.z - sM[b0+2]) * sInv[b0+2];
            a.w = __expf(sc.w - sM[b0+3]) * sInv[b0+3];
            *(float4*)(out + BB*NN + flat) = a;
            float4 cg = make_float4(cv.x + a.x, cv.y + a.y, cv.z + a.z, cv.w + a.w);
            *(float4*)(out + BB*NN + TT*BB + flat) = cg;
        }
    }
}

// ---------------------------------------------------------------------------
extern "C" void kernel_launch(void* const* d_in, const int* in_sizes, int n_in,
                              void* d_out, int out_size){
    const float*         dec  = (const float*)d_in[0];          // [B,H]
    const float*         enc  = (const float*)d_in[1];          // [T,B,N]
    const unsigned char* mask = (const unsigned char*)d_in[2];  // [T,B] (dtype auto-detected)
    const float*         cov  = (const float*)d_in[3];          // [T,B]
    const float*         Wd   = (const float*)d_in[4];          // [N,H]
    const float*         bd   = (const float*)d_in[5];          // [N]
    const float*         wc   = (const float*)d_in[6];          // [N]
    const float*         v    = (const float*)d_in[7];          // [N]
    float* out = (float*)d_out;  // c[B,N] | attn[T,B] | coverage_out[T,B]

    const int SMEM_MAIN = (2*4*NN + CHUNK)*4 + CHUNK + 32 + 44*4;  // ~65.8 KB
    cudaFuncSetAttribute(k_main, cudaFuncAttributeMaxDynamicSharedMemorySize, SMEM_MAIN);

    k_decfea<<<512, 128>>>(dec, Wd, bd, mask);
    k_main<<<dim3(SPL, BB), THR, SMEM_MAIN>>>(enc, cov, wc, v);
    k_combine<<<2*BB + (TT*BB/4 + 255)/256, 256>>>(cov, out);
}

// round 11
// speedup vs baseline: 1.9109x; 1.5545x over previous
#include <cuda_runtime.h>
#include <stdint.h>
#include <math.h>

#define TT 2048
#define BB 16
#define NN 2048
#define HH 1024
#define SPL 32
#define CHUNK 64    // timesteps per CTA before masking (~32 survive)
#define THR 256     // k_main threads (8 warps), 2 CTAs/SM

// scratch (device globals: no allocation allowed in kernel_launch)
__device__ float g_decfea[BB*NN];
__device__ float g_scores[TT*BB];     // only unmasked entries written
__device__ float g_m[BB*SPL];
__device__ float g_z[BB*SPL];
__device__ float g_acc[BB*SPL*NN];    // 4 MB
__device__ unsigned char g_mask8[TT*BB];

// single-MUFU tanh (sm_75+), abs err ~2e-4 — fine vs 1e-3 threshold
__device__ __forceinline__ float tanhfast(float x){
    float y;
    asm("tanh.approx.f32 %0, %1;" : "=f"(y) : "f"(x));
    return y;
}

__device__ __forceinline__ float4 ldcs4(const float4* p){
    float4 r;
    asm("ld.global.cs.v4.f32 {%0,%1,%2,%3}, [%4];"
        : "=f"(r.x), "=f"(r.y), "=f"(r.z), "=f"(r.w) : "l"(p));
    return r;
}

// ---------------------------------------------------------------------------
// Kernel 1: dec_fea[b,n] = dot(dec[b,:], Wd[n,:]) + bd[n].  (R9 version)
// 256 CTAs x 256 thr; warp owns one n-row; Wd preloaded (MLP 8); all 16 dec
// batches staged once in 64 KB dynamic smem; full-butterfly reduce.
// Also converts the padding mask to uint8 (dtype auto-detected).
// ---------------------------------------------------------------------------
__global__ __launch_bounds__(256) void k_decfea(
    const float* __restrict__ dec,
    const float* __restrict__ Wd,
    const float* __restrict__ bd,
    const unsigned char* __restrict__ mraw){
    extern __shared__ float sdec[];    // 64 KB
    {
        const unsigned int* w = (const unsigned int*)mraw;
        int is_word = 1;   // int32 (0/1) or float32 (0.0/1.0) storage
        #pragma unroll
        for (int i = 0; i < 32; ++i){
            unsigned int x = w[i];
            if (x != 0u && x != 1u && x != 0x3F800000u) is_word = 0;
        }
        int idx = blockIdx.x*256 + threadIdx.x;
        if (idx < TT*BB){
            unsigned char mv = is_word ? (unsigned char)(w[idx] != 0u)
                                       : (unsigned char)(mraw[idx] != 0);
            g_mask8[idx] = mv;
        }
    }

    int tid  = threadIdx.x;
    int wid  = tid >> 5, lane = tid & 31;

    int n = blockIdx.x*8 + wid;        // this warp's row
    const float4* wp = (const float4*)(Wd + (size_t)n*HH);

    float4 wv[8];
    #pragma unroll
    for (int ch = 0; ch < 8; ++ch) wv[ch] = wp[ch*32 + lane];

    {
        const float4* dg = (const float4*)dec;
        float4* sg = (float4*)sdec;
        #pragma unroll
        for (int i = 0; i < 16; ++i) sg[tid + i*256] = dg[tid + i*256];
    }
    __syncthreads();

    const float4* sd = (const float4*)sdec;
    float acc[BB];
    #pragma unroll
    for (int b = 0; b < BB; ++b) acc[b] = 0.f;

    #pragma unroll
    for (int ch = 0; ch < 8; ++ch){
        #pragma unroll
        for (int b = 0; b < BB; ++b){
            float4 d = sd[b*256 + ch*32 + lane];
            acc[b] += wv[ch].x*d.x + wv[ch].y*d.y + wv[ch].z*d.z + wv[ch].w*d.w;
        }
    }
    #pragma unroll
    for (int b = 0; b < BB; ++b){
        #pragma unroll
        for (int off = 16; off; off >>= 1)
            acc[b] += __shfl_xor_sync(0xffffffffu, acc[b], off);
    }
    float bias = bd[n];
    if (lane < BB) g_decfea[lane*NN + n] = acc[lane] + bias;
}

// ---------------------------------------------------------------------------
// Kernel 2: fused scores + online softmax + context partial, MASK-COMPACTED:
// masked timesteps (attn weight exactly 0) are never loaded nor computed —
// halves DRAM traffic and tanh work. grid (SPL, BB) = 512 CTAs; 256 thr;
// 2 CTAs/SM; register prefetch of the next 4 compacted rows.
// ---------------------------------------------------------------------------
__global__ __launch_bounds__(THR, 2) void k_main(
    const float* __restrict__ enc,
    const float* __restrict__ cov,
    const float* __restrict__ wc,
    const float* __restrict__ v)
{
    __shared__ float scov[CHUNK];
    __shared__ unsigned char smask[CHUNK];
    __shared__ short slist[CHUNK];    // compacted local t-indices (unmasked)
    __shared__ int   scnt;
    __shared__ float sred[8][5];      // [warp][score], padded
    __shared__ float sbc[4];
    int tid  = threadIdx.x;
    int wid  = tid >> 5, lane = tid & 31;
    int sp = blockIdx.x, b = blockIdx.y;
    int t0 = sp * CHUNK;

    if (tid < CHUNK){
        scov[tid]  = cov[(t0 + tid)*BB + b];
        smask[tid] = g_mask8[(t0 + tid)*BB + b];
    }
    int n0 = tid * 8;
    float4 df0 = *(const float4*)(g_decfea + b*NN + n0);
    float4 df1 = *(const float4*)(g_decfea + b*NN + n0 + 4);
    float4 w0  = *(const float4*)(wc + n0);
    float4 w1  = *(const float4*)(wc + n0 + 4);
    float4 v0  = *(const float4*)(v + n0);
    float4 v1  = *(const float4*)(v + n0 + 4);
    __syncthreads();

    // ---- build compacted unmasked list (warp 0, ballot + popc) ----
    if (tid < 32){
        unsigned mk0 = __ballot_sync(0xffffffffu, smask[tid] == 0);
        unsigned mk1 = __ballot_sync(0xffffffffu, smask[32 + tid] == 0);
        int c0 = __popc(mk0);
        int cnt = c0 + __popc(mk1);
        if (smask[tid] == 0)
            slist[__popc(mk0 & ((1u << tid) - 1u))] = (short)tid;
        if (smask[32 + tid] == 0)
            slist[c0 + __popc(mk1 & ((1u << tid) - 1u))] = (short)(32 + tid);
        __syncwarp();
        if (tid == 0){
            scnt = cnt;
            int padded = (cnt + 3) & ~3;
            for (int i = cnt; i < padded; ++i) slist[i] = slist[cnt > 0 ? cnt-1 : 0];
        }
    }
    __syncthreads();
    int cnt = scnt;

    float m = -INFINITY, Z = 0.f;
    float4 A0 = make_float4(0.f,0.f,0.f,0.f);
    float4 A1 = make_float4(0.f,0.f,0.f,0.f);

    if (cnt > 0){
        int nb = (cnt + 3) >> 2;
        // prefetch batch 0 (4 compacted rows)
        int li[4];
        float4 c0[4], c1[4];
        #pragma unroll
        for (int i = 0; i < 4; ++i){
            li[i] = slist[i];
            const float4* rp = (const float4*)(enc + ((size_t)(t0+li[i])*BB + b)*NN + n0);
            c0[i] = ldcs4(rp); c1[i] = ldcs4(rp + 1);
        }
        for (int it = 0; it < nb; ++it){
            bool havenext = (it + 1 < nb);
            int ni[4];
            float4 x0[4], x1[4];
            if (havenext){
                #pragma unroll
                for (int i = 0; i < 4; ++i){
                    ni[i] = slist[(it+1)*4 + i];
                    const float4* rp = (const float4*)(enc + ((size_t)(t0+ni[i])*BB + b)*NN + n0);
                    x0[i] = ldcs4(rp); x1[i] = ldcs4(rp + 1);
                }
            }
            float part[4];
            #pragma unroll
            for (int i = 0; i < 4; ++i){
                float cv = scov[li[i]];
                float p;
                p  = tanhfast(fmaf(cv, w0.x, c0[i].x + df0.x)) * v0.x;
                p += tanhfast(fmaf(cv, w0.y, c0[i].y + df0.y)) * v0.y;
                p += tanhfast(fmaf(cv, w0.z, c0[i].z + df0.z)) * v0.z;
                p += tanhfast(fmaf(cv, w0.w, c0[i].w + df0.w)) * v0.w;
                p += tanhfast(fmaf(cv, w1.x, c1[i].x + df1.x)) * v1.x;
                p += tanhfast(fmaf(cv, w1.y, c1[i].y + df1.y)) * v1.y;
                p += tanhfast(fmaf(cv, w1.z, c1[i].z + df1.z)) * v1.z;
                p += tanhfast(fmaf(cv, w1.w, c1[i].w + df1.w)) * v1.w;
                part[i] = p;
            }
            // stage 1: warp reduce 4 partials
            #pragma unroll
            for (int i = 0; i < 4; ++i)
                #pragma unroll
                for (int off = 16; off; off >>= 1)
                    part[i] += __shfl_xor_sync(0xffffffffu, part[i], off);
            if (lane == 0){
                #pragma unroll
                for (int i = 0; i < 4; ++i) sred[wid][i] = part[i];
            }
            __syncthreads();
            // stage 2: 32 threads, 8-lane groups, one score each
            if (tid < 32){
                int s  = tid >> 3;
                int ww = tid & 7;
                float val = sred[ww][s];
                val += __shfl_xor_sync(0xffffffffu, val, 1);
                val += __shfl_xor_sync(0xffffffffu, val, 2);
                val += __shfl_xor_sync(0xffffffffu, val, 4);
                if (ww == 0) sbc[s] = val;
            }
            __syncthreads();
            // scores for valid (non-pad) entries only
            if (tid < 4){
                int idx = it*4 + tid;
                if (idx < cnt) g_scores[(t0 + slist[idx])*BB + b] = sbc[tid];
            }
            float s[4];
            #pragma unroll
            for (int i = 0; i < 4; ++i)
                s[i] = (it*4 + i < cnt) ? sbc[i] : -INFINITY;

            // online softmax update (pads have s=-inf -> p=0, no contribution)
            float m2 = m;
            #pragma unroll
            for (int i = 0; i < 4; ++i) m2 = fmaxf(m2, s[i]);
            float sc = __expf(m - m2);             // m==-inf -> 0 (A still 0)
            float p[4];
            #pragma unroll
            for (int i = 0; i < 4; ++i) p[i] = __expf(s[i] - m2);
            Z = Z*sc + (p[0]+p[1]) + (p[2]+p[3]);
            float ax = A0.x*sc, ay = A0.y*sc, az = A0.z*sc, aw = A0.w*sc;
            float bx = A1.x*sc, by = A1.y*sc, bz = A1.z*sc, bw = A1.w*sc;
            #pragma unroll
            for (int i = 0; i < 4; ++i){
                ax = fmaf(p[i], c0[i].x, ax); ay = fmaf(p[i], c0[i].y, ay);
                az = fmaf(p[i], c0[i].z, az); aw = fmaf(p[i], c0[i].w, aw);
                bx = fmaf(p[i], c1[i].x, bx); by = fmaf(p[i], c1[i].y, by);
                bz = fmaf(p[i], c1[i].z, bz); bw = fmaf(p[i], c1[i].w, bw);
            }
            A0 = make_float4(ax, ay, az, aw);
            A1 = make_float4(bx, by, bz, bw);
            m = m2;

            if (havenext){
                #pragma unroll
                for (int i = 0; i < 4; ++i){
                    li[i] = ni[i]; c0[i] = x0[i]; c1[i] = x1[i];
                }
            }
        }
    }
    if (tid == 0){
        g_m[b*SPL + sp] = m;
        g_z[b*SPL + sp] = Z;
    }
    float4* op = (float4*)(g_acc + (size_t)(b*SPL + sp)*NN + n0);
    op[0] = A0; op[1] = A1;
}

// ---------------------------------------------------------------------------
// Kernel 3: combine. blocks 0..31: context c[b, n-half]. blocks 32..159:
// attn + coverage, float4 flat-indexed; masked entries -> attn 0 (never
// reads stale g_scores there).
// ---------------------------------------------------------------------------
__global__ void k_combine(const float* __restrict__ cov,
                          float* __restrict__ out){
    int tid = threadIdx.x;
    if (blockIdx.x < 2*BB){
        int b = blockIdx.x >> 1, h = blockIdx.x & 1;
        __shared__ float sw[SPL];
        if (tid < 32){
            float mv = g_m[b*SPL + tid];
            float zv = g_z[b*SPL + tid];
            float M = mv;
            #pragma unroll
            for (int off = 16; off; off >>= 1)
                M = fmaxf(M, __shfl_xor_sync(0xffffffffu, M, off));
            float Zs = zv * __expf(mv - M);
            #pragma unroll
            for (int off = 16; off; off >>= 1)
                Zs += __shfl_xor_sync(0xffffffffu, Zs, off);
            float inv = 1.0f / Zs;
            sw[tid] = __expf(mv - M) * inv;
        }
        __syncthreads();
        int n0 = h*1024 + tid*4;
        float4 r = make_float4(0.f,0.f,0.f,0.f);
        #pragma unroll
        for (int s = 0; s < SPL; ++s){
            float4 x = *(const float4*)(g_acc + (size_t)(b*SPL + s)*NN + n0);
            float wgt = sw[s];
            r.x = fmaf(wgt, x.x, r.x); r.y = fmaf(wgt, x.y, r.y);
            r.z = fmaf(wgt, x.z, r.z); r.w = fmaf(wgt, x.w, r.w);
        }
        *(float4*)(out + b*NN + n0) = r;
    } else {
        __shared__ float sM[BB], sInv[BB];
        if (tid < BB){
            int b = tid;
            float M = -INFINITY;
            #pragma unroll
            for (int s = 0; s < SPL; ++s) M = fmaxf(M, g_m[b*SPL + s]);
            float Zs = 0.f;
            #pragma unroll
            for (int s = 0; s < SPL; ++s) Zs += g_z[b*SPL + s] * __expf(g_m[b*SPL + s] - M);
            sM[b] = M; sInv[b] = 1.0f / Zs;
        }
        __syncthreads();
        int q = (blockIdx.x - 2*BB) * 256 + tid;    // 128 blocks -> 8192 quads
        int flat = q * 4;
        if (q < (TT*BB)/4){
            float4 sc = *(const float4*)(g_scores + flat);
            float4 cv = *(const float4*)(cov + flat);
            uchar4 mk = *(const uchar4*)(g_mask8 + flat);
            int b0 = flat & (BB-1);
            float4 a;
            a.x = mk.x ? 0.f : __expf(sc.x - sM[b0  ]) * sInv[b0  ];
            a.y = mk.y ? 0.f : __expf(sc.y - sM[b0+1]) * sInv[b0+1];
            a.z = mk.z ? 0.f : __expf(sc.z - sM[b0+2]) * sInv[b0+2];
            a.w = mk.w ? 0.f : __expf(sc.w - sM[b0+3]) * sInv[b0+3];
            *(float4*)(out + BB*NN + flat) = a;
            float4 cg = make_float4(cv.x + a.x, cv.y + a.y, cv.z + a.z, cv.w + a.w);
            *(float4*)(out + BB*NN + TT*BB + flat) = cg;
        }
    }
}

// ---------------------------------------------------------------------------
extern "C" void kernel_launch(void* const* d_in, const int* in_sizes, int n_in,
                              void* d_out, int out_size){
    const float*         dec  = (const float*)d_in[0];          // [B,H]
    const float*         enc  = (const float*)d_in[1];          // [T,B,N]
    const unsigned char* mask = (const unsigned char*)d_in[2];  // [T,B] (dtype auto-detected)
    const float*         cov  = (const float*)d_in[3];          // [T,B]
    const float*         Wd   = (const float*)d_in[4];          // [N,H]
    const float*         bd   = (const float*)d_in[5];          // [N]
    const float*         wc   = (const float*)d_in[6];          // [N]
    const float*         v    = (const float*)d_in[7];          // [N]
    float* out = (float*)d_out;  // c[B,N] | attn[T,B] | coverage_out[T,B]

    const int SMEM_DEC = BB*HH*4;                               // 64 KB
    cudaFuncSetAttribute(k_decfea, cudaFuncAttributeMaxDynamicSharedMemorySize, SMEM_DEC);

    k_decfea<<<256, 256, SMEM_DEC>>>(dec, Wd, bd, mask);
    k_main<<<dim3(SPL, BB), THR>>>(enc, cov, wc, v);
    k_combine<<<2*BB + (TT*BB/4 + 255)/256, 256>>>(cov, out);
}